// round 14
// baseline (speedup 1.0000x reference)
#include <cuda_runtime.h>
#include <cuda_bf16.h>
#include <math.h>
#include <stdint.h>

// Problem constants
#define Bq 2
#define Sq 2048
#define Dq 2048
#define Hq 8
#define KVq 2
#define HDq 256
#define WINDOWq 512
#define EPSq 1e-6f

#define BS_TOT (Bq * Sq)            // 4096
#define NQKV   (Hq * HDq + 2 * KVq * HDq)   // 3072 fused QKV width
#define KOFF   (Hq * HDq)                   // 2048
#define VOFF   (Hq * HDq + KVq * HDq)       // 2560

// ---------------------------------------------------------------------------
// Scratch (device globals; no allocation allowed)
// Packed bf16x3 format: uint32 = (bf16 lo << 16) | bf16 hi,  v ~= hi + lo
// ---------------------------------------------------------------------------
__device__ uint32_t g_h_pack   [BS_TOT * Dq];   // hidden packed [4096, 2048]
__device__ uint32_t g_wqkvT_pack[NQKV * Dq];    // fused qkv^T packed [3072, 2048]
__device__ uint32_t g_woT_pack [Dq * Hq * HDq]; // wo^T packed [2048, 2048]
__device__ float    g_qkvraw[BS_TOT * NQKV];    // [b*s, 3072] fp32
__device__ float    g_k[BS_TOT * KVq * HDq];    // [b, kv, s, 256]
__device__ float    g_v[BS_TOT * KVq * HDq];    // [b, kv, s, 256]
__device__ uint32_t g_attn_pack[BS_TOT * Hq * HDq]; // [b, s, h, 256] packed

// ---------------------------------------------------------------------------
// Helpers
// ---------------------------------------------------------------------------
__device__ __forceinline__ uint32_t pack_bf3(float v) {
    __nv_bfloat16 hb = __float2bfloat16_rn(v);
    float hf = __bfloat162float(hb);
    __nv_bfloat16 lb = __float2bfloat16_rn(v - hf);
    return ((uint32_t)__bfloat16_as_ushort(lb) << 16) |
           (uint32_t)__bfloat16_as_ushort(hb);
}

__device__ __forceinline__ uint32_t smem_u32p(const void* p) {
    uint32_t a;
    asm("{ .reg .u64 t; cvta.to.shared.u64 t, %1; cvt.u32.u64 %0, t; }" : "=r"(a) : "l"(p));
    return a;
}

__device__ __forceinline__ void cp_async16(uint32_t dst, const void* src) {
    asm volatile("cp.async.cg.shared.global [%0], [%1], 16;\n" :: "r"(dst), "l"(src));
}

__device__ __forceinline__ uint32_t prmt(uint32_t a, uint32_t b, uint32_t sel) {
    uint32_t r;
    asm("prmt.b32 %0, %1, %2, %3;" : "=r"(r) : "r"(a), "r"(b), "r"(sel));
    return r;
}

// m16n8k16 bf16 mma (sm_80+ PTX)
__device__ __forceinline__ void mma_bf16(float c[4], const uint32_t a[4], const uint32_t b[2]) {
    asm volatile(
        "mma.sync.aligned.m16n8k16.row.col.f32.bf16.bf16.f32 "
        "{%0,%1,%2,%3}, {%4,%5,%6,%7}, {%8,%9}, {%0,%1,%2,%3};"
        : "+f"(c[0]), "+f"(c[1]), "+f"(c[2]), "+f"(c[3])
        : "r"(a[0]), "r"(a[1]), "r"(a[2]), "r"(a[3]), "r"(b[0]), "r"(b[1]));
}

// ---------------------------------------------------------------------------
// bf16x3 split-precision GEMM — R12 conflict-free layout, BK=32 via TWO
// independent 16-k half-tiles per stage (each half identical to R12's tile,
// so the LDS128 pattern stays provably conflict-free). Halves iteration
// count 128 -> 64: half the syncthreads/wait/pipeline-tail overhead.
// Stage layout: [Ah0 | Ah1 | Bh0 | Bh1], 8KB each = 32KB; 3 stages = 96KB.
// ---------------------------------------------------------------------------
#define GSTAGES 3
#define GROWU32 16
#define GHTILE_U32 (128 * GROWU32)               // 2048 u32 per half-tile
#define GHTILE_BYTES (GHTILE_U32 * 4)            // 8192
#define GSTAGE_BYTES (4 * GHTILE_BYTES)          // 32768
#define GSMEM_REQ (GSTAGES * GSTAGE_BYTES)       // 98304

__global__ __launch_bounds__(256) void gemm_bf3(int M, int N, int K,
                                                const uint32_t* __restrict__ Ap,
                                                const uint32_t* __restrict__ Bp,
                                                float* __restrict__ C) {
    extern __shared__ char smem_raw[];
    uint32_t* smem_u = (uint32_t*)smem_raw;
    const uint32_t smem_base = smem_u32p(smem_raw);

    const int tid = threadIdx.x;
    const int wid = tid >> 5;
    const int lane = tid & 31;
    const int g = lane >> 2;          // 0..7
    const int t = lane & 3;           // 0..3

    const int bm = blockIdx.y;
    const int bn = blockIdx.x;
    const int warp_m = (wid & 1) * 64;    // 2 warps over M
    const int warp_n = (wid >> 1) * 32;   // 4 warps over N

    const uint32_t* Ab = Ap + (size_t)bm * 128 * K;
    const uint32_t* Bb = Bp + (size_t)bn * 128 * K;
    const int niters = K / 32;

    const int l_row0 = tid >> 1;               // 0..127
    const int l_c40  = (tid & 1) << 1;         // 0 or 2 (uint4 col)

    float c[4][4][4];
#pragma unroll
    for (int mt = 0; mt < 4; mt++)
#pragma unroll
        for (int nt = 0; nt < 4; nt++)
#pragma unroll
            for (int i = 0; i < 4; i++) c[mt][nt][i] = 0.f;

    // Stage loader: both 16-k halves of a 32-k chunk
    auto load_stage = [&](int stage, int chunk) {
        const uint32_t sb = smem_base + stage * GSTAGE_BYTES;
        const size_t koff = (size_t)chunk * 32;
#pragma unroll
        for (int kh = 0; kh < 2; kh++) {
            const uint32_t a_s = sb + kh * GHTILE_BYTES;
            const uint32_t b_s = sb + (2 + kh) * GHTILE_BYTES;
#pragma unroll
            for (int j = 0; j < 2; j++) {
                int row = l_row0, c4 = l_c40 + j;
                uint32_t so = (row * GROWU32 + c4 * 4) * 4;
                size_t go = (size_t)row * K + koff + kh * 16 + c4 * 4;
                cp_async16(a_s + so, Ab + go);
                cp_async16(b_s + so, Bb + go);
            }
        }
        asm volatile("cp.async.commit_group;" ::: "memory");
    };

    // Prologue: stages 0, 1
    load_stage(0, 0);
    load_stage(1, 1);

    for (int it = 0; it < niters; it++) {
        if (it + 2 < niters) {
            load_stage((it + 2) % GSTAGES, it + 2);
            asm volatile("cp.async.wait_group 2;" ::: "memory");
        } else if (it + 1 < niters) {
            asm volatile("cp.async.wait_group 1;" ::: "memory");
        } else {
            asm volatile("cp.async.wait_group 0;" ::: "memory");
        }
        __syncthreads();

        const int s = it % GSTAGES;
#pragma unroll
        for (int kh = 0; kh < 2; kh++) {
            const uint32_t* As = smem_u + s * (GSTAGE_BYTES / 4) + kh * GHTILE_U32;
            const uint32_t* Bs = smem_u + s * (GSTAGE_BYTES / 4) + (2 + kh) * GHTILE_U32;

            uint32_t ahi[4][4], alo[4][4], bhi[4][2], blo[4][2];
#pragma unroll
            for (int mt = 0; mt < 4; mt++) {
                const int m0 = warp_m + mt * 16;
                uint4 qa = *(const uint4*)&As[(m0 + g)     * GROWU32 + 4 * t];
                uint4 qb = *(const uint4*)&As[(m0 + 8 + g) * GROWU32 + 4 * t];
                ahi[mt][0] = prmt(qa.x, qa.y, 0x5410u); alo[mt][0] = prmt(qa.x, qa.y, 0x7632u);
                ahi[mt][1] = prmt(qb.x, qb.y, 0x5410u); alo[mt][1] = prmt(qb.x, qb.y, 0x7632u);
                ahi[mt][2] = prmt(qa.z, qa.w, 0x5410u); alo[mt][2] = prmt(qa.z, qa.w, 0x7632u);
                ahi[mt][3] = prmt(qb.z, qb.w, 0x5410u); alo[mt][3] = prmt(qb.z, qb.w, 0x7632u);
            }
#pragma unroll
            for (int nt = 0; nt < 4; nt++) {
                const int n0 = warp_n + nt * 8;
                uint4 r = *(const uint4*)&Bs[(n0 + g) * GROWU32 + 4 * t];
                bhi[nt][0] = prmt(r.x, r.y, 0x5410u); blo[nt][0] = prmt(r.x, r.y, 0x7632u);
                bhi[nt][1] = prmt(r.z, r.w, 0x5410u); blo[nt][1] = prmt(r.z, r.w, 0x7632u);
            }
#pragma unroll
            for (int mt = 0; mt < 4; mt++)
#pragma unroll
                for (int nt = 0; nt < 4; nt++) {
                    mma_bf16(c[mt][nt], alo[mt], bhi[nt]);
                    mma_bf16(c[mt][nt], ahi[mt], blo[nt]);
                    mma_bf16(c[mt][nt], ahi[mt], bhi[nt]);
                }
        }
        __syncthreads();
    }

    float* Cb = C + (size_t)(bm * 128) * N + bn * 128;
#pragma unroll
    for (int mt = 0; mt < 4; mt++) {
#pragma unroll
        for (int nt = 0; nt < 4; nt++) {
            const int r0 = warp_m + mt * 16 + g;
            const int c0 = warp_n + nt * 8 + t * 2;
            *(float2*)(Cb + (size_t)r0 * N + c0)       = make_float2(c[mt][nt][0], c[mt][nt][1]);
            *(float2*)(Cb + (size_t)(r0 + 8) * N + c0) = make_float2(c[mt][nt][2], c[mt][nt][3]);
        }
    }
}

// ---------------------------------------------------------------------------
// Elementwise pack (float4 -> uint4)
// ---------------------------------------------------------------------------
__global__ __launch_bounds__(256) void pack_kernel(const float* __restrict__ in,
                                                   uint32_t* __restrict__ out, int n4) {
    int i = blockIdx.x * 256 + threadIdx.x;
    if (i < n4) {
        float4 v = ((const float4*)in)[i];
        uint4 o;
        o.x = pack_bf3(v.x); o.y = pack_bf3(v.y);
        o.z = pack_bf3(v.z); o.w = pack_bf3(v.w);
        ((uint4*)out)[i] = o;
    }
}

// Transpose + pack:  w[K,N] -> wt[N,K] packed
__global__ __launch_bounds__(256) void transp_pack_kernel(const float* __restrict__ w,
                                                          uint32_t* __restrict__ wt,
                                                          int Kd, int Nd) {
    __shared__ float tile[32][33];
    const int n0 = blockIdx.x * 32, k0 = blockIdx.y * 32;
    const int tx = threadIdx.x, ty = threadIdx.y;
#pragma unroll
    for (int j = ty; j < 32; j += 8)
        tile[j][tx] = w[(size_t)(k0 + j) * Nd + n0 + tx];
    __syncthreads();
#pragma unroll
    for (int j = ty; j < 32; j += 8)
        wt[(size_t)(n0 + j) * Kd + k0 + tx] = pack_bf3(tile[tx][j]);
}

// ---------------------------------------------------------------------------
// RMSNorm + RoPE for K from fused qkvraw; RMSNorm for V.
// (Q's norm+rope is fused into the attention kernel.)
// ---------------------------------------------------------------------------
__global__ __launch_bounds__(256) void norm_rope_kernel(const float* __restrict__ raw,
                                                        const float* __restrict__ cosb,
                                                        const float* __restrict__ sinb,
                                                        const float* __restrict__ w,
                                                        float* __restrict__ out,
                                                        int NH, int col_off) {
    const int bs = blockIdx.x;
    const int h  = blockIdx.y;
    const int t  = threadIdx.x;
    const int b  = bs / Sq;
    const int s  = bs % Sq;

    float x = raw[(size_t)bs * NQKV + col_off + h * HDq + t];

    __shared__ float red[8];
    float v = x * x;
#pragma unroll
    for (int o = 16; o; o >>= 1) v += __shfl_xor_sync(0xFFFFFFFFu, v, o);
    if ((t & 31) == 0) red[t >> 5] = v;
    __syncthreads();
    float tot = 0.f;
#pragma unroll
    for (int i = 0; i < 8; i++) tot += red[i];
    float inv = rsqrtf(tot * (1.f / HDq) + EPSq);
    float y = x * inv * w[t];

    __shared__ float sy[HDq];
    sy[t] = y;
    __syncthreads();
    float rot = (t < 128) ? -sy[t + 128] : sy[t - 128];
    float c = cosb[(size_t)bs * HDq + t];
    float sn = sinb[(size_t)bs * HDq + t];
    float o = y * c + rot * sn;

    out[(((size_t)b * NH + h) * Sq + s) * HDq + t] = o;
}

__global__ __launch_bounds__(256) void norm_v_kernel(const float* __restrict__ raw,
                                                     float* __restrict__ out) {
    const int bs = blockIdx.x;
    const int h  = blockIdx.y;
    const int t  = threadIdx.x;
    const int b  = bs / Sq;
    const int s  = bs % Sq;

    float x = raw[(size_t)bs * NQKV + VOFF + h * HDq + t];

    __shared__ float red[8];
    float v = x * x;
#pragma unroll
    for (int o = 16; o; o >>= 1) v += __shfl_xor_sync(0xFFFFFFFFu, v, o);
    if ((t & 31) == 0) red[t >> 5] = v;
    __syncthreads();
    float tot = 0.f;
#pragma unroll
    for (int i = 0; i < 8; i++) tot += red[i];
    float inv = rsqrtf(tot * (1.f / HDq) + EPSq);

    out[(((size_t)b * KVq + h) * Sq + s) * HDq + t] = x * inv;
}

// ---------------------------------------------------------------------------
// Sliding-window attention: 2 q/warp, cp.async double-buffered K/V tiles,
// and Q RMSNorm+RoPE fused in-register (reads qkvraw directly).
// With the lane+32e layout, RoPE pairs (d, d+128) are e <-> e+-4 in the SAME
// lane; the norm sum is one 8-FMA + 5-shfl warp reduce.
// ---------------------------------------------------------------------------
#define ATK 16
#define AQPB 32
#define ATILE_F (ATK * HDq)                  // 4096 floats / 16KB
#define ASMEM_REQ (4 * ATILE_F * 4)          // 65536 bytes

__global__ __launch_bounds__(512) void attn_kernel(const float* __restrict__ qkvraw,
                                                   const float* __restrict__ cosb,
                                                   const float* __restrict__ sinb,
                                                   const float* __restrict__ qnw,
                                                   const float* __restrict__ Kt,
                                                   const float* __restrict__ Vt,
                                                   uint32_t* __restrict__ Opack) {
    extern __shared__ float asmem[];
    const uint32_t smem_base = smem_u32p(asmem);

    const int bh = blockIdx.y;
    const int b = bh / Hq, h = bh % Hq;
    const int hk = h / (Hq / KVq);
    const int qbase = blockIdx.x * AQPB;
    const int warp = threadIdx.x >> 5;
    const int lane = threadIdx.x & 31;
    const int q0 = qbase + warp;          // first query
    const int q1 = q0 + 16;               // second query

    // Per-lane norm weight fragment
    float wnf[8];
#pragma unroll
    for (int e = 0; e < 8; e++) wnf[e] = qnw[lane + 32 * e];

    // Fused Q load + RMSNorm + RoPE for a query -> qf[8]
    auto load_q = [&](int q, float qf[8]) {
        const size_t bs = (size_t)b * Sq + q;
        const float* xp = qkvraw + bs * NQKV + h * HDq;
        float x[8];
        float ss = 0.f;
#pragma unroll
        for (int e = 0; e < 8; e++) { x[e] = xp[lane + 32 * e]; ss = fmaf(x[e], x[e], ss); }
#pragma unroll
        for (int o = 16; o; o >>= 1) ss += __shfl_xor_sync(0xFFFFFFFFu, ss, o);
        const float inv = rsqrtf(ss * (1.f / HDq) + EPSq);
        float y[8];
#pragma unroll
        for (int e = 0; e < 8; e++) y[e] = x[e] * inv * wnf[e];
        const float* cp = cosb + bs * HDq;
        const float* sp = sinb + bs * HDq;
#pragma unroll
        for (int e = 0; e < 8; e++) {
            float rot = (e < 4) ? -y[e + 4] : y[e - 4];
            qf[e] = y[e] * cp[lane + 32 * e] + rot * sp[lane + 32 * e];
        }
    };

    float qf0[8], qf1[8];
    load_q(q0, qf0);
    load_q(q1, qf1);

    const float* Kb = Kt + ((size_t)b * KVq + hk) * Sq * HDq;
    const float* Vb = Vt + ((size_t)b * KVq + hk) * Sq * HDq;

    const int lo = max(0, qbase - (WINDOWq - 1));
    const int hi = qbase + AQPB - 1;
    const int ntiles = (hi - lo) / ATK + 1;

    auto issue_tile = [&](int ti) {
        const int t0 = lo + ti * ATK;
        const int nrows = min(ATK, hi - t0 + 1);
        const uint32_t kb = smem_base + (uint32_t)(ti & 1) * (2 * ATILE_F * 4);
        const uint32_t vb = kb + ATILE_F * 4;
        for (int i = threadIdx.x; i < nrows * 64; i += 512) {
            int r = i >> 6;
            int c4 = i & 63;
            uint32_t so = (r * HDq + c4 * 4) * 4;
            size_t go = (size_t)(t0 + r) * HDq + c4 * 4;
            cp_async16(kb + so, Kb + go);
            cp_async16(vb + so, Vb + go);
        }
        asm volatile("cp.async.commit_group;" ::: "memory");
    };

    float m0 = -1e30f, l0 = 0.f, m1 = -1e30f, l1 = 0.f;
    float o0[8], o1[8];
#pragma unroll
    for (int e = 0; e < 8; e++) { o0[e] = 0.f; o1[e] = 0.f; }

    issue_tile(0);

    for (int ti = 0; ti < ntiles; ti++) {
        if (ti + 1 < ntiles) {
            issue_tile(ti + 1);
            asm volatile("cp.async.wait_group 1;" ::: "memory");
        } else {
            asm volatile("cp.async.wait_group 0;" ::: "memory");
        }
        __syncthreads();

        const float* Ks = asmem + (ti & 1) * (2 * ATILE_F);
        const float* Vs = Ks + ATILE_F;

        const int t0 = lo + ti * ATK;
        const int nrows = min(ATK, hi - t0 + 1);
        const int jmin0 = max(0, (q0 - (WINDOWq - 1)) - t0);
        const int jmax0 = min(nrows, q0 - t0 + 1);
        const int jmin1 = max(0, (q1 - (WINDOWq - 1)) - t0);
        const int jmax1 = min(nrows, q1 - t0 + 1);
        const int jlo = min(jmin0, jmin1);
        const int jhi = max(jmax0, jmax1);

        for (int j = jlo; j < jhi; j++) {
            float k[8];
#pragma unroll
            for (int e = 0; e < 8; e++) k[e] = Ks[j * HDq + lane + 32 * e];

            float s0 = 0.f, s1 = 0.f;
#pragma unroll
            for (int e = 0; e < 8; e++) {
                s0 = fmaf(qf0[e], k[e], s0);
                s1 = fmaf(qf1[e], k[e], s1);
            }
#pragma unroll
            for (int off = 16; off; off >>= 1) {
                s0 += __shfl_xor_sync(0xFFFFFFFFu, s0, off);
                s1 += __shfl_xor_sync(0xFFFFFFFFu, s1, off);
            }

            float v[8];
#pragma unroll
            for (int e = 0; e < 8; e++) v[e] = Vs[j * HDq + lane + 32 * e];

            const bool a0 = (j >= jmin0) & (j < jmax0);   // warp-uniform
            const bool a1 = (j >= jmin1) & (j < jmax1);   // warp-uniform

            if (a0) {
                if (s0 > m0) {
                    float sc = __expf(m0 - s0);
                    l0 *= sc;
#pragma unroll
                    for (int e = 0; e < 8; e++) o0[e] *= sc;
                    m0 = s0;
                }
                float p = __expf(s0 - m0);
                l0 += p;
#pragma unroll
                for (int e = 0; e < 8; e++) o0[e] = fmaf(p, v[e], o0[e]);
            }
            if (a1) {
                if (s1 > m1) {
                    float sc = __expf(m1 - s1);
                    l1 *= sc;
#pragma unroll
                    for (int e = 0; e < 8; e++) o1[e] *= sc;
                    m1 = s1;
                }
                float p = __expf(s1 - m1);
                l1 += p;
#pragma unroll
                for (int e = 0; e < 8; e++) o1[e] = fmaf(p, v[e], o1[e]);
            }
        }
        __syncthreads();   // protect buffer (ti&1) before reuse at ti+2
    }

    const float invl0 = 1.f / l0;
    const float invl1 = 1.f / l1;
    uint32_t* op0 = Opack + (((size_t)b * Sq + q0) * Hq + h) * HDq;
    uint32_t* op1 = Opack + (((size_t)b * Sq + q1) * Hq + h) * HDq;
#pragma unroll
    for (int e = 0; e < 8; e++) {
        op0[lane + 32 * e] = pack_bf3(o0[e] * invl0);
        op1[lane + 32 * e] = pack_bf3(o1[e] * invl1);
    }
}

// ---------------------------------------------------------------------------
extern "C" void kernel_launch(void* const* d_in, const int* in_sizes, int n_in,
                              void* d_out, int out_size) {
    (void)in_sizes; (void)n_in; (void)out_size;
    const float* hidden = (const float*)d_in[0];
    const float* cosb   = (const float*)d_in[1];
    const float* sinb   = (const float*)d_in[2];
    // d_in[3] = attention_mask: replaced exactly by the sliding-window range.
    const float* wq     = (const float*)d_in[4];
    const float* wk     = (const float*)d_in[5];
    const float* wv     = (const float*)d_in[6];
    const float* wo     = (const float*)d_in[7];
    const float* qnw    = (const float*)d_in[8];
    const float* knw    = (const float*)d_in[9];
    float* out = (float*)d_out;

    uint32_t *h_pack, *wqkvT_pack, *woT_pack, *attn_pack;
    float *qkvraw, *kn, *vn;
    cudaGetSymbolAddress((void**)&h_pack,     g_h_pack);
    cudaGetSymbolAddress((void**)&wqkvT_pack, g_wqkvT_pack);
    cudaGetSymbolAddress((void**)&woT_pack,   g_woT_pack);
    cudaGetSymbolAddress((void**)&qkvraw,     g_qkvraw);
    cudaGetSymbolAddress((void**)&kn,         g_k);
    cudaGetSymbolAddress((void**)&vn,         g_v);
    cudaGetSymbolAddress((void**)&attn_pack,  g_attn_pack);

    cudaFuncSetAttribute(gemm_bf3, cudaFuncAttributeMaxDynamicSharedMemorySize, GSMEM_REQ);
    cudaFuncSetAttribute(attn_kernel, cudaFuncAttributeMaxDynamicSharedMemorySize, ASMEM_REQ);

    // 0) pack hidden + fused weight transposes (packed bf16 hi/lo)
    {
        int n4 = BS_TOT * Dq / 4;
        pack_kernel<<<(n4 + 255) / 256, 256>>>(hidden, h_pack, n4);
        dim3 tb(32, 8);
        transp_pack_kernel<<<dim3(Hq * HDq / 32,  Dq / 32), tb>>>(wq, wqkvT_pack, Dq, Hq * HDq);
        transp_pack_kernel<<<dim3(KVq * HDq / 32, Dq / 32), tb>>>(wk, wqkvT_pack + (size_t)KOFF * Dq, Dq, KVq * HDq);
        transp_pack_kernel<<<dim3(KVq * HDq / 32, Dq / 32), tb>>>(wv, wqkvT_pack + (size_t)VOFF * Dq, Dq, KVq * HDq);
        transp_pack_kernel<<<dim3(Dq / 32, Hq * HDq / 32),  tb>>>(wo, woT_pack, Hq * HDq, Dq);
    }

    // 1) Fused QKV projection (bf16x3, M=4096, N=3072, K=2048)
    gemm_bf3<<<dim3(NQKV / 128, BS_TOT / 128), 256, GSMEM_REQ>>>(BS_TOT, NQKV, Dq,
                                                                 h_pack, wqkvT_pack, qkvraw);

    // 2) RMSNorm + RoPE (K), RMSNorm (V). Q is fused into attention.
    {
        dim3 gk(BS_TOT, KVq);
        norm_rope_kernel<<<gk, 256>>>(qkvraw, cosb, sinb, knw, kn, KVq, KOFF);
        norm_v_kernel<<<gk, 256>>>(qkvraw, vn);
    }

    // 3) Sliding-window attention (Q norm+rope fused) -> [b, s, h, hd] packed
    {
        dim3 ga(Sq / AQPB, Bq * Hq);
        attn_kernel<<<ga, 512, ASMEM_REQ>>>(qkvraw, cosb, sinb, qnw, kn, vn, attn_pack);
    }

    // 4) Output projection (bf16x3, M=4096, N=2048, K=2048)
    gemm_bf3<<<dim3(Dq / 128, BS_TOT / 128), 256, GSMEM_REQ>>>(BS_TOT, Dq, Hq * HDq,
                                                               attn_pack, woT_pack, out);
}

// round 15
// speedup vs baseline: 1.1104x; 1.1104x over previous
#include <cuda_runtime.h>
#include <cuda_bf16.h>
#include <math.h>
#include <stdint.h>

// Problem constants
#define Bq 2
#define Sq 2048
#define Dq 2048
#define Hq 8
#define KVq 2
#define HDq 256
#define WINDOWq 512
#define EPSq 1e-6f

#define BS_TOT (Bq * Sq)            // 4096
#define NQKV   (Hq * HDq + 2 * KVq * HDq)   // 3072 fused QKV width
#define KOFF   (Hq * HDq)                   // 2048
#define VOFF   (Hq * HDq + KVq * HDq)       // 2560

// ---------------------------------------------------------------------------
// Scratch (device globals; no allocation allowed)
// Packed bf16x3 format: uint32 = (bf16 lo << 16) | bf16 hi,  v ~= hi + lo
// ---------------------------------------------------------------------------
__device__ uint32_t g_h_pack   [BS_TOT * Dq];   // hidden packed [4096, 2048]
__device__ uint32_t g_wqkvT_pack[NQKV * Dq];    // fused qkv^T packed [3072, 2048]
__device__ uint32_t g_woT_pack [Dq * Hq * HDq]; // wo^T packed [2048, 2048]
__device__ float    g_qkvraw[BS_TOT * NQKV];    // [b*s, 3072] fp32
__device__ float    g_k[BS_TOT * KVq * HDq];    // [b, kv, s, 256]
__device__ float    g_v[BS_TOT * KVq * HDq];    // [b, kv, s, 256]
__device__ uint32_t g_attn_pack[BS_TOT * Hq * HDq]; // [b, s, h, 256] packed

// ---------------------------------------------------------------------------
// Helpers
// ---------------------------------------------------------------------------
__device__ __forceinline__ uint32_t pack_bf3(float v) {
    __nv_bfloat16 hb = __float2bfloat16_rn(v);
    float hf = __bfloat162float(hb);
    __nv_bfloat16 lb = __float2bfloat16_rn(v - hf);
    return ((uint32_t)__bfloat16_as_ushort(lb) << 16) |
           (uint32_t)__bfloat16_as_ushort(hb);
}

__device__ __forceinline__ uint32_t smem_u32p(const void* p) {
    uint32_t a;
    asm("{ .reg .u64 t; cvta.to.shared.u64 t, %1; cvt.u32.u64 %0, t; }" : "=r"(a) : "l"(p));
    return a;
}

__device__ __forceinline__ void cp_async16(uint32_t dst, const void* src) {
    asm volatile("cp.async.cg.shared.global [%0], [%1], 16;\n" :: "r"(dst), "l"(src));
}

__device__ __forceinline__ uint32_t prmt(uint32_t a, uint32_t b, uint32_t sel) {
    uint32_t r;
    asm("prmt.b32 %0, %1, %2, %3;" : "=r"(r) : "r"(a), "r"(b), "r"(sel));
    return r;
}

// m16n8k16 bf16 mma (sm_80+ PTX)
__device__ __forceinline__ void mma_bf16(float c[4], const uint32_t a[4], const uint32_t b[2]) {
    asm volatile(
        "mma.sync.aligned.m16n8k16.row.col.f32.bf16.bf16.f32 "
        "{%0,%1,%2,%3}, {%4,%5,%6,%7}, {%8,%9}, {%0,%1,%2,%3};"
        : "+f"(c[0]), "+f"(c[1]), "+f"(c[2]), "+f"(c[3])
        : "r"(a[0]), "r"(a[1]), "r"(a[2]), "r"(a[3]), "r"(b[0]), "r"(b[1]));
}

// ---------------------------------------------------------------------------
// bf16x3 split-precision GEMM — FROZEN at R12 (conflict-free LDS128 layout,
// BK=16, 48KB smem; R14's BK=32 variant regressed via occupancy/regs).
//   C[M,N] = A[M,K] @ Bt[N,K]^T,  c += alo*bhi + ahi*blo + ahi*bhi
// ---------------------------------------------------------------------------
#define GSTAGES 3
#define GROWU32 16
#define GTILE_U32 (128 * GROWU32)                // 2048 u32
#define GTILE_BYTES (GTILE_U32 * 4)              // 8192
#define GSTAGE_BYTES (2 * GTILE_BYTES)           // 16384
#define GSMEM_REQ (GSTAGES * GSTAGE_BYTES)       // 49152

__global__ __launch_bounds__(256) void gemm_bf3(int M, int N, int K,
                                                const uint32_t* __restrict__ Ap,
                                                const uint32_t* __restrict__ Bp,
                                                float* __restrict__ C) {
    extern __shared__ char smem_raw[];
    uint32_t* smem_u = (uint32_t*)smem_raw;
    const uint32_t smem_base = smem_u32p(smem_raw);

    const int tid = threadIdx.x;
    const int wid = tid >> 5;
    const int lane = tid & 31;
    const int g = lane >> 2;          // 0..7
    const int t = lane & 3;           // 0..3

    const int bm = blockIdx.y;
    const int bn = blockIdx.x;
    const int warp_m = (wid & 1) * 64;    // 2 warps over M
    const int warp_n = (wid >> 1) * 32;   // 4 warps over N

    const uint32_t* Ab = Ap + (size_t)bm * 128 * K;
    const uint32_t* Bb = Bp + (size_t)bn * 128 * K;
    const int niters = K / 16;

    const int l_row0 = tid >> 1;               // 0..127
    const int l_c40  = (tid & 1) << 1;         // 0 or 2 (uint4 col)

    float c[4][4][4];
#pragma unroll
    for (int mt = 0; mt < 4; mt++)
#pragma unroll
        for (int nt = 0; nt < 4; nt++)
#pragma unroll
            for (int i = 0; i < 4; i++) c[mt][nt][i] = 0.f;

    // Prologue: stages 0, 1
#pragma unroll
    for (int st = 0; st < 2; st++) {
        const uint32_t a_s = smem_base + st * GSTAGE_BYTES;
        const uint32_t b_s = a_s + GTILE_BYTES;
        const size_t koff = (size_t)st * 16;
#pragma unroll
        for (int j = 0; j < 2; j++) {
            int row = l_row0, c4 = l_c40 + j;
            uint32_t so = (row * GROWU32 + c4 * 4) * 4;
            size_t go = (size_t)row * K + koff + c4 * 4;
            cp_async16(a_s + so, Ab + go);
            cp_async16(b_s + so, Bb + go);
        }
        asm volatile("cp.async.commit_group;" ::: "memory");
    }

    for (int it = 0; it < niters; it++) {
        if (it + 2 < niters) {
            const int rs = (it + 2) % GSTAGES;
            const uint32_t a_s = smem_base + rs * GSTAGE_BYTES;
            const uint32_t b_s = a_s + GTILE_BYTES;
            const size_t koff = (size_t)(it + 2) * 16;
#pragma unroll
            for (int j = 0; j < 2; j++) {
                int row = l_row0, c4 = l_c40 + j;
                uint32_t so = (row * GROWU32 + c4 * 4) * 4;
                size_t go = (size_t)row * K + koff + c4 * 4;
                cp_async16(a_s + so, Ab + go);
                cp_async16(b_s + so, Bb + go);
            }
            asm volatile("cp.async.commit_group;" ::: "memory");
            asm volatile("cp.async.wait_group 2;" ::: "memory");
        } else if (it + 1 < niters) {
            asm volatile("cp.async.wait_group 1;" ::: "memory");
        } else {
            asm volatile("cp.async.wait_group 0;" ::: "memory");
        }
        __syncthreads();

        const int s = it % GSTAGES;
        const uint32_t* As = smem_u + s * (GSTAGE_BYTES / 4);
        const uint32_t* Bs = As + GTILE_U32;

        uint32_t ahi[4][4], alo[4][4], bhi[4][2], blo[4][2];
#pragma unroll
        for (int mt = 0; mt < 4; mt++) {
            const int m0 = warp_m + mt * 16;
            uint4 qa = *(const uint4*)&As[(m0 + g)     * GROWU32 + 4 * t];
            uint4 qb = *(const uint4*)&As[(m0 + 8 + g) * GROWU32 + 4 * t];
            ahi[mt][0] = prmt(qa.x, qa.y, 0x5410u); alo[mt][0] = prmt(qa.x, qa.y, 0x7632u);
            ahi[mt][1] = prmt(qb.x, qb.y, 0x5410u); alo[mt][1] = prmt(qb.x, qb.y, 0x7632u);
            ahi[mt][2] = prmt(qa.z, qa.w, 0x5410u); alo[mt][2] = prmt(qa.z, qa.w, 0x7632u);
            ahi[mt][3] = prmt(qb.z, qb.w, 0x5410u); alo[mt][3] = prmt(qb.z, qb.w, 0x7632u);
        }
#pragma unroll
        for (int nt = 0; nt < 4; nt++) {
            const int n0 = warp_n + nt * 8;
            uint4 r = *(const uint4*)&Bs[(n0 + g) * GROWU32 + 4 * t];
            bhi[nt][0] = prmt(r.x, r.y, 0x5410u); blo[nt][0] = prmt(r.x, r.y, 0x7632u);
            bhi[nt][1] = prmt(r.z, r.w, 0x5410u); blo[nt][1] = prmt(r.z, r.w, 0x7632u);
        }
#pragma unroll
        for (int mt = 0; mt < 4; mt++)
#pragma unroll
            for (int nt = 0; nt < 4; nt++) {
                mma_bf16(c[mt][nt], alo[mt], bhi[nt]);
                mma_bf16(c[mt][nt], ahi[mt], blo[nt]);
                mma_bf16(c[mt][nt], ahi[mt], bhi[nt]);
            }
        __syncthreads();
    }

    float* Cb = C + (size_t)(bm * 128) * N + bn * 128;
#pragma unroll
    for (int mt = 0; mt < 4; mt++) {
#pragma unroll
        for (int nt = 0; nt < 4; nt++) {
            const int r0 = warp_m + mt * 16 + g;
            const int c0 = warp_n + nt * 8 + t * 2;
            *(float2*)(Cb + (size_t)r0 * N + c0)       = make_float2(c[mt][nt][0], c[mt][nt][1]);
            *(float2*)(Cb + (size_t)(r0 + 8) * N + c0) = make_float2(c[mt][nt][2], c[mt][nt][3]);
        }
    }
}

// ---------------------------------------------------------------------------
// Elementwise pack (float4 -> uint4)
// ---------------------------------------------------------------------------
__global__ __launch_bounds__(256) void pack_kernel(const float* __restrict__ in,
                                                   uint32_t* __restrict__ out, int n4) {
    int i = blockIdx.x * 256 + threadIdx.x;
    if (i < n4) {
        float4 v = ((const float4*)in)[i];
        uint4 o;
        o.x = pack_bf3(v.x); o.y = pack_bf3(v.y);
        o.z = pack_bf3(v.z); o.w = pack_bf3(v.w);
        ((uint4*)out)[i] = o;
    }
}

// Transpose + pack:  w[K,N] -> wt[N,K] packed
__global__ __launch_bounds__(256) void transp_pack_kernel(const float* __restrict__ w,
                                                          uint32_t* __restrict__ wt,
                                                          int Kd, int Nd) {
    __shared__ float tile[32][33];
    const int n0 = blockIdx.x * 32, k0 = blockIdx.y * 32;
    const int tx = threadIdx.x, ty = threadIdx.y;
#pragma unroll
    for (int j = ty; j < 32; j += 8)
        tile[j][tx] = w[(size_t)(k0 + j) * Nd + n0 + tx];
    __syncthreads();
#pragma unroll
    for (int j = ty; j < 32; j += 8)
        wt[(size_t)(n0 + j) * Kd + k0 + tx] = pack_bf3(tile[tx][j]);
}

// ---------------------------------------------------------------------------
// RMSNorm + RoPE for K from fused qkvraw; RMSNorm for V.
// (Q's norm+rope is fused into the attention kernel.)
// ---------------------------------------------------------------------------
__global__ __launch_bounds__(256) void norm_rope_kernel(const float* __restrict__ raw,
                                                        const float* __restrict__ cosb,
                                                        const float* __restrict__ sinb,
                                                        const float* __restrict__ w,
                                                        float* __restrict__ out,
                                                        int NH, int col_off) {
    const int bs = blockIdx.x;
    const int h  = blockIdx.y;
    const int t  = threadIdx.x;
    const int b  = bs / Sq;
    const int s  = bs % Sq;

    float x = raw[(size_t)bs * NQKV + col_off + h * HDq + t];

    __shared__ float red[8];
    float v = x * x;
#pragma unroll
    for (int o = 16; o; o >>= 1) v += __shfl_xor_sync(0xFFFFFFFFu, v, o);
    if ((t & 31) == 0) red[t >> 5] = v;
    __syncthreads();
    float tot = 0.f;
#pragma unroll
    for (int i = 0; i < 8; i++) tot += red[i];
    float inv = rsqrtf(tot * (1.f / HDq) + EPSq);
    float y = x * inv * w[t];

    __shared__ float sy[HDq];
    sy[t] = y;
    __syncthreads();
    float rot = (t < 128) ? -sy[t + 128] : sy[t - 128];
    float c = cosb[(size_t)bs * HDq + t];
    float sn = sinb[(size_t)bs * HDq + t];
    float o = y * c + rot * sn;

    out[(((size_t)b * NH + h) * Sq + s) * HDq + t] = o;
}

__global__ __launch_bounds__(256) void norm_v_kernel(const float* __restrict__ raw,
                                                     float* __restrict__ out) {
    const int bs = blockIdx.x;
    const int h  = blockIdx.y;
    const int t  = threadIdx.x;
    const int b  = bs / Sq;
    const int s  = bs % Sq;

    float x = raw[(size_t)bs * NQKV + VOFF + h * HDq + t];

    __shared__ float red[8];
    float v = x * x;
#pragma unroll
    for (int o = 16; o; o >>= 1) v += __shfl_xor_sync(0xFFFFFFFFu, v, o);
    if ((t & 31) == 0) red[t >> 5] = v;
    __syncthreads();
    float tot = 0.f;
#pragma unroll
    for (int i = 0; i < 8; i++) tot += red[i];
    float inv = rsqrtf(tot * (1.f / HDq) + EPSq);

    out[(((size_t)b * KVq + h) * Sq + s) * HDq + t] = x * inv;
}

// ---------------------------------------------------------------------------
// Sliding-window attention: 2 q/warp, cp.async double-buffered K/V tiles,
// Q RMSNorm+RoPE fused in-register (reads qkvraw directly; g_q eliminated).
// With the lane+32e layout, RoPE pairs (d, d+128) are e <-> e+-4 in the SAME
// lane; the norm sum is one 8-FMA + 5-shfl warp reduce.
// ---------------------------------------------------------------------------
#define ATK 16
#define AQPB 32
#define ATILE_F (ATK * HDq)                  // 4096 floats / 16KB
#define ASMEM_REQ (4 * ATILE_F * 4)          // 65536 bytes

__global__ __launch_bounds__(512) void attn_kernel(const float* __restrict__ qkvraw,
                                                   const float* __restrict__ cosb,
                                                   const float* __restrict__ sinb,
                                                   const float* __restrict__ qnw,
                                                   const float* __restrict__ Kt,
                                                   const float* __restrict__ Vt,
                                                   uint32_t* __restrict__ Opack) {
    extern __shared__ float asmem[];
    const uint32_t smem_base = smem_u32p(asmem);

    const int bh = blockIdx.y;
    const int b = bh / Hq, h = bh % Hq;
    const int hk = h / (Hq / KVq);
    const int qbase = blockIdx.x * AQPB;
    const int warp = threadIdx.x >> 5;
    const int lane = threadIdx.x & 31;
    const int q0 = qbase + warp;          // first query
    const int q1 = q0 + 16;               // second query

    // Per-lane norm weight fragment
    float wnf[8];
#pragma unroll
    for (int e = 0; e < 8; e++) wnf[e] = qnw[lane + 32 * e];

    // Fused Q load + RMSNorm + RoPE for a query -> qf[8]
    auto load_q = [&](int q, float qf[8]) {
        const size_t bs = (size_t)b * Sq + q;
        const float* xp = qkvraw + bs * NQKV + h * HDq;
        float x[8];
        float ss = 0.f;
#pragma unroll
        for (int e = 0; e < 8; e++) { x[e] = xp[lane + 32 * e]; ss = fmaf(x[e], x[e], ss); }
#pragma unroll
        for (int o = 16; o; o >>= 1) ss += __shfl_xor_sync(0xFFFFFFFFu, ss, o);
        const float inv = rsqrtf(ss * (1.f / HDq) + EPSq);
        float y[8];
#pragma unroll
        for (int e = 0; e < 8; e++) y[e] = x[e] * inv * wnf[e];
        const float* cp = cosb + bs * HDq;
        const float* sp = sinb + bs * HDq;
#pragma unroll
        for (int e = 0; e < 8; e++) {
            float rot = (e < 4) ? -y[e + 4] : y[e - 4];
            qf[e] = y[e] * cp[lane + 32 * e] + rot * sp[lane + 32 * e];
        }
    };

    float qf0[8], qf1[8];
    load_q(q0, qf0);
    load_q(q1, qf1);

    const float* Kb = Kt + ((size_t)b * KVq + hk) * Sq * HDq;
    const float* Vb = Vt + ((size_t)b * KVq + hk) * Sq * HDq;

    const int lo = max(0, qbase - (WINDOWq - 1));
    const int hi = qbase + AQPB - 1;
    const int ntiles = (hi - lo) / ATK + 1;

    auto issue_tile = [&](int ti) {
        const int t0 = lo + ti * ATK;
        const int nrows = min(ATK, hi - t0 + 1);
        const uint32_t kb = smem_base + (uint32_t)(ti & 1) * (2 * ATILE_F * 4);
        const uint32_t vb = kb + ATILE_F * 4;
        for (int i = threadIdx.x; i < nrows * 64; i += 512) {
            int r = i >> 6;
            int c4 = i & 63;
            uint32_t so = (r * HDq + c4 * 4) * 4;
            size_t go = (size_t)(t0 + r) * HDq + c4 * 4;
            cp_async16(kb + so, Kb + go);
            cp_async16(vb + so, Vb + go);
        }
        asm volatile("cp.async.commit_group;" ::: "memory");
    };

    float m0 = -1e30f, l0 = 0.f, m1 = -1e30f, l1 = 0.f;
    float o0[8], o1[8];
#pragma unroll
    for (int e = 0; e < 8; e++) { o0[e] = 0.f; o1[e] = 0.f; }

    issue_tile(0);

    for (int ti = 0; ti < ntiles; ti++) {
        if (ti + 1 < ntiles) {
            issue_tile(ti + 1);
            asm volatile("cp.async.wait_group 1;" ::: "memory");
        } else {
            asm volatile("cp.async.wait_group 0;" ::: "memory");
        }
        __syncthreads();

        const float* Ks = asmem + (ti & 1) * (2 * ATILE_F);
        const float* Vs = Ks + ATILE_F;

        const int t0 = lo + ti * ATK;
        const int nrows = min(ATK, hi - t0 + 1);
        const int jmin0 = max(0, (q0 - (WINDOWq - 1)) - t0);
        const int jmax0 = min(nrows, q0 - t0 + 1);
        const int jmin1 = max(0, (q1 - (WINDOWq - 1)) - t0);
        const int jmax1 = min(nrows, q1 - t0 + 1);
        const int jlo = min(jmin0, jmin1);
        const int jhi = max(jmax0, jmax1);

        for (int j = jlo; j < jhi; j++) {
            float k[8];
#pragma unroll
            for (int e = 0; e < 8; e++) k[e] = Ks[j * HDq + lane + 32 * e];

            float s0 = 0.f, s1 = 0.f;
#pragma unroll
            for (int e = 0; e < 8; e++) {
                s0 = fmaf(qf0[e], k[e], s0);
                s1 = fmaf(qf1[e], k[e], s1);
            }
#pragma unroll
            for (int off = 16; off; off >>= 1) {
                s0 += __shfl_xor_sync(0xFFFFFFFFu, s0, off);
                s1 += __shfl_xor_sync(0xFFFFFFFFu, s1, off);
            }

            float v[8];
#pragma unroll
            for (int e = 0; e < 8; e++) v[e] = Vs[j * HDq + lane + 32 * e];

            const bool a0 = (j >= jmin0) & (j < jmax0);   // warp-uniform
            const bool a1 = (j >= jmin1) & (j < jmax1);   // warp-uniform

            if (a0) {
                if (s0 > m0) {
                    float sc = __expf(m0 - s0);
                    l0 *= sc;
#pragma unroll
                    for (int e = 0; e < 8; e++) o0[e] *= sc;
                    m0 = s0;
                }
                float p = __expf(s0 - m0);
                l0 += p;
#pragma unroll
                for (int e = 0; e < 8; e++) o0[e] = fmaf(p, v[e], o0[e]);
            }
            if (a1) {
                if (s1 > m1) {
                    float sc = __expf(m1 - s1);
                    l1 *= sc;
#pragma unroll
                    for (int e = 0; e < 8; e++) o1[e] *= sc;
                    m1 = s1;
                }
                float p = __expf(s1 - m1);
                l1 += p;
#pragma unroll
                for (int e = 0; e < 8; e++) o1[e] = fmaf(p, v[e], o1[e]);
            }
        }
        __syncthreads();   // protect buffer (ti&1) before reuse at ti+2
    }

    const float invl0 = 1.f / l0;
    const float invl1 = 1.f / l1;
    uint32_t* op0 = Opack + (((size_t)b * Sq + q0) * Hq + h) * HDq;
    uint32_t* op1 = Opack + (((size_t)b * Sq + q1) * Hq + h) * HDq;
#pragma unroll
    for (int e = 0; e < 8; e++) {
        op0[lane + 32 * e] = pack_bf3(o0[e] * invl0);
        op1[lane + 32 * e] = pack_bf3(o1[e] * invl1);
    }
}

// ---------------------------------------------------------------------------
extern "C" void kernel_launch(void* const* d_in, const int* in_sizes, int n_in,
                              void* d_out, int out_size) {
    (void)in_sizes; (void)n_in; (void)out_size;
    const float* hidden = (const float*)d_in[0];
    const float* cosb   = (const float*)d_in[1];
    const float* sinb   = (const float*)d_in[2];
    // d_in[3] = attention_mask: replaced exactly by the sliding-window range.
    const float* wq     = (const float*)d_in[4];
    const float* wk     = (const float*)d_in[5];
    const float* wv     = (const float*)d_in[6];
    const float* wo     = (const float*)d_in[7];
    const float* qnw    = (const float*)d_in[8];
    const float* knw    = (const float*)d_in[9];
    float* out = (float*)d_out;

    uint32_t *h_pack, *wqkvT_pack, *woT_pack, *attn_pack;
    float *qkvraw, *kn, *vn;
    cudaGetSymbolAddress((void**)&h_pack,     g_h_pack);
    cudaGetSymbolAddress((void**)&wqkvT_pack, g_wqkvT_pack);
    cudaGetSymbolAddress((void**)&woT_pack,   g_woT_pack);
    cudaGetSymbolAddress((void**)&qkvraw,     g_qkvraw);
    cudaGetSymbolAddress((void**)&kn,         g_k);
    cudaGetSymbolAddress((void**)&vn,         g_v);
    cudaGetSymbolAddress((void**)&attn_pack,  g_attn_pack);

    cudaFuncSetAttribute(gemm_bf3, cudaFuncAttributeMaxDynamicSharedMemorySize, GSMEM_REQ);
    cudaFuncSetAttribute(attn_kernel, cudaFuncAttributeMaxDynamicSharedMemorySize, ASMEM_REQ);

    // 0) pack hidden + fused weight transposes (packed bf16 hi/lo)
    {
        int n4 = BS_TOT * Dq / 4;
        pack_kernel<<<(n4 + 255) / 256, 256>>>(hidden, h_pack, n4);
        dim3 tb(32, 8);
        transp_pack_kernel<<<dim3(Hq * HDq / 32,  Dq / 32), tb>>>(wq, wqkvT_pack, Dq, Hq * HDq);
        transp_pack_kernel<<<dim3(KVq * HDq / 32, Dq / 32), tb>>>(wk, wqkvT_pack + (size_t)KOFF * Dq, Dq, KVq * HDq);
        transp_pack_kernel<<<dim3(KVq * HDq / 32, Dq / 32), tb>>>(wv, wqkvT_pack + (size_t)VOFF * Dq, Dq, KVq * HDq);
        transp_pack_kernel<<<dim3(Dq / 32, Hq * HDq / 32),  tb>>>(wo, woT_pack, Hq * HDq, Dq);
    }

    // 1) Fused QKV projection (bf16x3, M=4096, N=3072, K=2048)
    gemm_bf3<<<dim3(NQKV / 128, BS_TOT / 128), 256, GSMEM_REQ>>>(BS_TOT, NQKV, Dq,
                                                                 h_pack, wqkvT_pack, qkvraw);

    // 2) RMSNorm + RoPE (K), RMSNorm (V). Q is fused into attention.
    {
        dim3 gk(BS_TOT, KVq);
        norm_rope_kernel<<<gk, 256>>>(qkvraw, cosb, sinb, knw, kn, KVq, KOFF);
        norm_v_kernel<<<gk, 256>>>(qkvraw, vn);
    }

    // 3) Sliding-window attention (Q norm+rope fused) -> [b, s, h, hd] packed
    {
        dim3 ga(Sq / AQPB, Bq * Hq);
        attn_kernel<<<ga, 512, ASMEM_REQ>>>(qkvraw, cosb, sinb, qnw, kn, vn, attn_pack);
    }

    // 4) Output projection (bf16x3, M=4096, N=2048, K=2048)
    gemm_bf3<<<dim3(Dq / 128, BS_TOT / 128), 256, GSMEM_REQ>>>(BS_TOT, Dq, Hq * HDq,
                                                               attn_pack, woT_pack, out);
}